// round 2
// baseline (speedup 1.0000x reference)
#include <cuda_runtime.h>
#include <math.h>

// ---------------- static device scratch (no runtime allocation) ----------------
__device__ float g_h1[(size_t)16*64*128*128];   // enc stage1 out / dec upsample1 out
__device__ float g_a [(size_t)16*128*64*64];
__device__ float g_b [(size_t)16*128*64*64];
__device__ float g_c [(size_t)16*32*64*64];     // resblock mid (32ch)
__device__ float g_z [(size_t)16*64*64*64];     // pre-VQ latents
__device__ float g_q [(size_t)16*64*64*64];     // quantized latents
__device__ int   g_idx[65536];
__device__ float g_c2[512];
__device__ int   g_counts[512];
__device__ float g_partial[256];

static const int NB = 16;

// d_out layout (flattened tuple):
// [0] loss | [1 .. 1+1048576) x_rec | [1048577] perplexity |
// [1048578 .. +33554432) encodings | [34603010 .. +4194304) quantized
#define OFF_XREC   1
#define OFF_PERP   1048577
#define OFF_ENC    1048578
#define OFF_QUANT  34603010

// ---------------- generic direct conv (thread per output, warp along W) ----------------
template<int CIN,int COUT,int K,int S,int P,bool RELU_IN,bool RELU_OUT,bool HAS_BIAS>
__global__ void conv_k(const float* __restrict__ in, const float* __restrict__ w,
                       const float* __restrict__ bias, float* __restrict__ out,
                       int H, int W, int OH, int OW)
{
    int idx = blockIdx.x * blockDim.x + threadIdx.x;
    int total = NB * COUT * OH * OW;
    if (idx >= total) return;
    int ow = idx % OW; int t = idx / OW;
    int oh = t % OH;   t /= OH;
    int oc = t % COUT; int n = t / COUT;

    float acc = HAS_BIAS ? __ldg(&bias[oc]) : 0.0f;
    const float* inN = in + (size_t)n * CIN * H * W;
    const float* wO  = w  + (size_t)oc * CIN * K * K;
    int ihb = oh * S - P;
    int iwb = ow * S - P;

#pragma unroll 4
    for (int ci = 0; ci < CIN; ++ci) {
        const float* inC = inN + (size_t)ci * H * W;
        const float* wC  = wO + ci * K * K;
#pragma unroll
        for (int kh = 0; kh < K; ++kh) {
            int ih = ihb + kh;
            if ((unsigned)ih >= (unsigned)H) continue;
#pragma unroll
            for (int kw = 0; kw < K; ++kw) {
                int iw = iwb + kw;
                if ((unsigned)iw >= (unsigned)W) continue;
                float v = inC[(size_t)ih * W + iw];
                if (RELU_IN) v = fmaxf(v, 0.0f);
                acc = fmaf(v, __ldg(&wC[kh * K + kw]), acc);
            }
        }
    }
    if (RELU_OUT) acc = fmaxf(acc, 0.0f);
    out[idx] = acc;
}

// ---------------- 1x1 conv (optionally relu-in, bias, residual add) ----------------
template<int CIN,int COUT,bool RELU_IN,bool HAS_BIAS,bool ADD_RES>
__global__ void conv1x1_k(const float* __restrict__ in, const float* __restrict__ w,
                          const float* __restrict__ bias, const float* __restrict__ res,
                          float* __restrict__ out, int HW)
{
    int idx = blockIdx.x * blockDim.x + threadIdx.x;
    int total = NB * COUT * HW;
    if (idx >= total) return;
    int hw = idx % HW; int t = idx / HW;
    int oc = t % COUT; int n = t / COUT;

    float acc = HAS_BIAS ? __ldg(&bias[oc]) : 0.0f;
    const float* inN = in + (size_t)n * CIN * HW + hw;
    const float* wO  = w + oc * CIN;
#pragma unroll 8
    for (int ci = 0; ci < CIN; ++ci) {
        float v = inN[(size_t)ci * HW];
        if (RELU_IN) v = fmaxf(v, 0.0f);
        acc = fmaf(v, __ldg(&wO[ci]), acc);
    }
    if (ADD_RES) acc += res[idx];
    out[idx] = acc;
}

// ---------------- transposed conv 4x4 stride2 pad1, gather form ----------------
// weight layout: (CIN, COUT, 4, 4)  [torch ConvTranspose2d]
template<int CIN,int COUT,bool RELU_OUT>
__global__ void convT_k(const float* __restrict__ in, const float* __restrict__ w,
                        const float* __restrict__ bias, float* __restrict__ out,
                        int H, int W)
{
    int OH = 2 * H, OW = 2 * W;
    int idx = blockIdx.x * blockDim.x + threadIdx.x;
    int total = NB * COUT * OH * OW;
    if (idx >= total) return;
    int ow = idx % OW; int t = idx / OW;
    int oh = t % OH;   t /= OH;
    int oc = t % COUT; int n = t / COUT;

    // valid taps: kh in {kh0, kh0+2}, ih = (oh+1-kh)/2
    int kh0 = (oh + 1) & 1; int ih0 = (oh + 1 - kh0) >> 1;
    int kw0 = (ow + 1) & 1; int iw0 = (ow + 1 - kw0) >> 1;
    bool vh0 = (ih0 < H), vh1 = (ih0 - 1 >= 0);
    bool vw0 = (iw0 < W), vw1 = (iw0 - 1 >= 0);

    float acc = __ldg(&bias[oc]);
    const float* inN = in + (size_t)n * CIN * H * W;
    int w00 = oc * 16 + kh0 * 4 + kw0;
    int i00 = ih0 * W + iw0;

#pragma unroll 4
    for (int ci = 0; ci < CIN; ++ci) {
        const float* ip = inN + (size_t)ci * H * W;
        const float* wp = w + (size_t)ci * COUT * 16;
        if (vh0 && vw0) acc = fmaf(ip[i00],         __ldg(&wp[w00]),      acc);
        if (vh0 && vw1) acc = fmaf(ip[i00 - 1],     __ldg(&wp[w00 + 2]),  acc);
        if (vh1 && vw0) acc = fmaf(ip[i00 - W],     __ldg(&wp[w00 + 8]),  acc);
        if (vh1 && vw1) acc = fmaf(ip[i00 - W - 1], __ldg(&wp[w00 + 10]), acc);
    }
    if (RELU_OUT) acc = fmaxf(acc, 0.0f);
    out[idx] = acc;
}

// ---------------- VQ ----------------
__global__ void vq_prep(const float* __restrict__ cb)
{
    int k = blockIdx.x * blockDim.x + threadIdx.x;
    if (k < 512) {
        float s = 0.0f;
        const float* c = cb + k * 64;
#pragma unroll
        for (int d = 0; d < 64; ++d) s = fmaf(c[d], c[d], s);
        g_c2[k] = s;
        g_counts[k] = 0;
    }
}

// one thread per latent row; codebook staged through smem in 64-codeword chunks.
// IMPORTANT: replicate the reference distance formula exactly:
//     dist = (|z|^2 + |c|^2) - 2*(z . c)    (all fp32)
// The large |z|^2 term quantizes distances onto the fp32 grid; jnp.argmin then
// breaks the resulting ties toward the LOWEST index. Dropping |z|^2 (a per-row
// constant) changes which entry wins whenever the reference has a rounded tie.
__global__ void vq_argmin(const float* __restrict__ cb)
{
    __shared__ float sc[64 * 64];
    __shared__ float sc2[64];
    __shared__ int   hist[512];
    int tid = threadIdx.x;
    for (int i = tid; i < 512; i += 256) hist[i] = 0;

    int r  = blockIdx.x * 256 + tid;     // r in [0, 65536)
    int n  = r >> 12;
    int hw = r & 4095;
    const float* zp = g_z + (size_t)n * 64 * 4096 + hw;

    float zr[64];
#pragma unroll
    for (int d = 0; d < 64; ++d) zr[d] = zp[(size_t)d * 4096];

    // |z|^2 in plain fp32 sequential order (matches jnp.sum semantics closely;
    // any tiny ordering difference is absorbed by the same grid rounding)
    float z2 = 0.0f;
#pragma unroll
    for (int d = 0; d < 64; ++d) z2 = fmaf(zr[d], zr[d], z2);

    float best = 3.4e38f;
    int bi = 0;
    for (int chunk = 0; chunk < 8; ++chunk) {
        __syncthreads();
        for (int i = tid; i < 4096; i += 256) sc[i] = cb[chunk * 4096 + i];
        if (tid < 64) sc2[tid] = g_c2[chunk * 64 + tid];
        __syncthreads();
        for (int c = 0; c < 64; ++c) {
            const float4* cv = (const float4*)&sc[c * 64];
            float d0 = 0, d1 = 0, d2 = 0, d3 = 0;
#pragma unroll
            for (int j = 0; j < 16; ++j) {
                float4 v = cv[j];
                d0 = fmaf(v.x, zr[4 * j + 0], d0);
                d1 = fmaf(v.y, zr[4 * j + 1], d1);
                d2 = fmaf(v.z, zr[4 * j + 2], d2);
                d3 = fmaf(v.w, zr[4 * j + 3], d3);
            }
            float dot = (d0 + d1) + (d2 + d3);
            // exact reference order: (z2 + c2) - 2*dot, each op rounded fp32
            float dist = __fadd_rn(__fadd_rn(z2, sc2[c]), -2.0f * dot);
            if (dist < best) { best = dist; bi = chunk * 64 + c; }
        }
    }
    g_idx[r] = bi;
    atomicAdd(&hist[bi], 1);
    __syncthreads();
    for (int i = tid; i < 512; i += 256)
        if (hist[i]) atomicAdd(&g_counts[i], hist[i]);
}

__global__ void fill_zero2(float2* __restrict__ p, int n2)
{
    int i = blockIdx.x * blockDim.x + threadIdx.x;
    if (i < n2) p[i] = make_float2(0.0f, 0.0f);
}

// quantized write (internal + output), one-hot scatter, per-block SSE partial
__global__ void vq_quant(const float* __restrict__ cb, float* __restrict__ out_enc,
                         float* __restrict__ out_quant)
{
    __shared__ float red[256];
    int tid = threadIdx.x;
    int r   = blockIdx.x * 256 + tid;
    int k   = g_idx[r];
    int n   = r >> 12;
    int hw  = r & 4095;
    size_t base = (size_t)n * 64 * 4096 + hw;
    const float* zp = g_z + base;
    float* qp = g_q + base;
    float* oq = out_quant + base;
    const float* ck = cb + k * 64;

    float sse = 0.0f;
#pragma unroll
    for (int d = 0; d < 64; ++d) {
        float qv = __ldg(&ck[d]);
        float zv = zp[(size_t)d * 4096];
        qp[(size_t)d * 4096] = qv;
        oq[(size_t)d * 4096] = qv;
        float df = qv - zv;
        sse = fmaf(df, df, sse);
    }
    out_enc[(size_t)r * 512 + k] = 1.0f;

    red[tid] = sse;
    __syncthreads();
    for (int s = 128; s > 0; s >>= 1) {
        if (tid < s) red[tid] += red[tid + s];
        __syncthreads();
    }
    if (tid == 0) g_partial[blockIdx.x] = red[0];
}

__global__ void vq_final(float* __restrict__ d_out)
{
    __shared__ float sh[512];
    int t = threadIdx.x;
    float avg = (float)g_counts[t] * (1.0f / 65536.0f);
    sh[t] = avg * logf(avg + 1e-10f);
    __syncthreads();
    for (int s = 256; s > 0; s >>= 1) {
        if (t < s) sh[t] += sh[t + s];
        __syncthreads();
    }
    if (t == 0) {
        d_out[OFF_PERP] = expf(-sh[0]);
        double acc = 0.0;
        for (int i = 0; i < 256; ++i) acc += (double)g_partial[i];
        d_out[0] = (float)(1.25 * acc / (65536.0 * 64.0));
    }
}

// ---------------- host launcher ----------------
static inline int grd(long long total) { return (int)((total + 255) / 256); }

extern "C" void kernel_launch(void* const* d_in, const int* in_sizes, int n_in,
                              void* d_out_v, int out_size)
{
    const float* x    = (const float*)d_in[0];
    const float* ew1  = (const float*)d_in[1];
    const float* eb1  = (const float*)d_in[2];
    const float* ew2  = (const float*)d_in[3];
    const float* eb2  = (const float*)d_in[4];
    const float* ew3  = (const float*)d_in[5];
    const float* eb3  = (const float*)d_in[6];
    const float* er1a = (const float*)d_in[7];
    const float* er1b = (const float*)d_in[8];
    const float* er2a = (const float*)d_in[9];
    const float* er2b = (const float*)d_in[10];
    const float* pwW  = (const float*)d_in[11];
    const float* pb   = (const float*)d_in[12];
    const float* cb   = (const float*)d_in[13];
    const float* dw1  = (const float*)d_in[14];
    const float* db1  = (const float*)d_in[15];
    const float* dr1a = (const float*)d_in[16];
    const float* dr1b = (const float*)d_in[17];
    const float* dr2a = (const float*)d_in[18];
    const float* dr2b = (const float*)d_in[19];
    const float* dtw1 = (const float*)d_in[20];
    const float* dtb1 = (const float*)d_in[21];
    const float* dtw2 = (const float*)d_in[22];
    const float* dtb2 = (const float*)d_in[23];
    float* d_out = (float*)d_out_v;

    void* p;
    float *h1, *a, *b, *c, *z, *q;
    cudaGetSymbolAddress(&p, g_h1); h1 = (float*)p;
    cudaGetSymbolAddress(&p, g_a);  a  = (float*)p;
    cudaGetSymbolAddress(&p, g_b);  b  = (float*)p;
    cudaGetSymbolAddress(&p, g_c);  c  = (float*)p;
    cudaGetSymbolAddress(&p, g_z);  z  = (float*)p;
    cudaGetSymbolAddress(&p, g_q);  q  = (float*)p;

    const long long S1 = 16LL * 64 * 128 * 128;   // 16.8M
    const long long S2 = 16LL * 128 * 64 * 64;    // 8.4M
    const long long S3 = 16LL * 32 * 64 * 64;     // 2.1M
    const long long SZ = 16LL * 64 * 64 * 64;     // 4.2M

    // ---- encoder ----
    conv_k<1, 64, 4, 2, 1, false, true,  true ><<<grd(S1), 256>>>(x,  ew1, eb1, h1, 256, 256, 128, 128);
    conv_k<64,128, 4, 2, 1, false, true,  true ><<<grd(S2), 256>>>(h1, ew2, eb2, a,  128, 128, 64, 64);
    conv_k<128,128,3, 1, 1, false, false, true ><<<grd(S2), 256>>>(a,  ew3, eb3, b,  64, 64, 64, 64);
    // resblock 1: b -> a
    conv_k<128, 32, 3, 1, 1, true, false, false><<<grd(S3), 256>>>(b, er1a, nullptr, c, 64, 64, 64, 64);
    conv1x1_k<32, 128, true, false, true><<<grd(S2), 256>>>(c, er1b, nullptr, b, a, 4096);
    // resblock 2: a -> b
    conv_k<128, 32, 3, 1, 1, true, false, false><<<grd(S3), 256>>>(a, er2a, nullptr, c, 64, 64, 64, 64);
    conv1x1_k<32, 128, true, false, true><<<grd(S2), 256>>>(c, er2b, nullptr, a, b, 4096);
    // pre-VQ projection (relu fused on input)
    conv1x1_k<128, 64, true, true, false><<<grd(SZ), 256>>>(b, pwW, pb, nullptr, z, 4096);

    // ---- vector quantizer ----
    vq_prep<<<2, 256>>>(cb);
    vq_argmin<<<256, 256>>>(cb);
    fill_zero2<<<grd(16777216), 256>>>((float2*)(d_out + OFF_ENC), 16777216);
    vq_quant<<<256, 256>>>(cb, d_out + OFF_ENC, d_out + OFF_QUANT);
    vq_final<<<1, 512>>>(d_out);

    // ---- decoder ----
    conv_k<64, 128, 3, 1, 1, false, false, true><<<grd(S2), 256>>>(q, dw1, db1, a, 64, 64, 64, 64);
    // resblock 1: a -> b
    conv_k<128, 32, 3, 1, 1, true, false, false><<<grd(S3), 256>>>(a, dr1a, nullptr, c, 64, 64, 64, 64);
    conv1x1_k<32, 128, true, false, true><<<grd(S2), 256>>>(c, dr1b, nullptr, a, b, 4096);
    // resblock 2: b -> a
    conv_k<128, 32, 3, 1, 1, true, false, false><<<grd(S3), 256>>>(b, dr2a, nullptr, c, 64, 64, 64, 64);
    conv1x1_k<32, 128, true, false, true><<<grd(S2), 256>>>(c, dr2b, nullptr, b, a, 4096);
    // upsample
    convT_k<128, 64, true ><<<grd(S1), 256>>>(a,  dtw1, dtb1, h1, 64, 64);
    convT_k<64, 1,  false><<<grd(16LL * 256 * 256), 256>>>(h1, dtw2, dtb2, d_out + OFF_XREC, 128, 128);
}

// round 3
// speedup vs baseline: 3.1237x; 3.1237x over previous
#include <cuda_runtime.h>
#include <math.h>

// ---------------- static device scratch ----------------
__device__ float g_h1[(size_t)16*64*128*128];
__device__ float g_a [(size_t)16*128*64*64];
__device__ float g_b [(size_t)16*128*64*64];
__device__ float g_c [(size_t)16*32*64*64];
__device__ float g_z [(size_t)16*64*64*64];
__device__ float g_q [(size_t)16*64*64*64];
__device__ int   g_idx[65536];
__device__ float g_c2[512];
__device__ int   g_counts[512];
__device__ float g_partial[256];

#define OFF_XREC   1
#define OFF_PERP   1048577
#define OFF_ENC    1048578
#define OFF_QUANT  34603010

// ============ 3x3 s1 p1 conv on 64x64; thread = 4 rows x 8 oc ============
template<int CIN, bool RELU_IN, bool RELU_OUT, bool HAS_BIAS>
__global__ __launch_bounds__(256)
void conv3_t(const float* __restrict__ in, const float* __restrict__ w,
             const float* __restrict__ bias, float* __restrict__ out, int COUT)
{
    __shared__ float s_in[2][18*66];
    __shared__ float s_w[CIN*72];
    const int tid = threadIdx.x;
    const int tx = tid & 63, ty = tid >> 6;
    const int tile = blockIdx.x, n = blockIdx.y, ocg = blockIdx.z;

    for (int i = tid; i < CIN*72; i += 256) {
        int ci = i / 72, rem = i % 72, o = rem / 9, t = rem % 9;
        s_w[i] = w[((size_t)(ocg*8 + o) * CIN + ci) * 9 + t];
    }
    const int ih0 = tile*16 - 1;
    const float* inN = in + (size_t)n * CIN * 4096;

    { // stage ci 0
        const float* ip = inN;
        for (int i = tid; i < 18*66; i += 256) {
            int r = i / 66, c = i % 66;
            int ih = ih0 + r, iw = c - 1;
            float v = ((unsigned)ih < 64u && (unsigned)iw < 64u) ? ip[ih*64+iw] : 0.0f;
            if (RELU_IN) v = fmaxf(v, 0.0f);
            s_in[0][i] = v;
        }
    }
    __syncthreads();

    float acc[32];
#pragma unroll
    for (int o = 0; o < 8; ++o) {
        float b0 = HAS_BIAS ? __ldg(&bias[ocg*8+o]) : 0.0f;
#pragma unroll
        for (int j = 0; j < 4; ++j) acc[j*8+o] = b0;
    }

#pragma unroll 1
    for (int ci = 0; ci < CIN; ++ci) {
        if (ci + 1 < CIN) {
            const float* ip = inN + (size_t)(ci+1) * 4096;
            float* sb = s_in[(ci+1)&1];
            for (int i = tid; i < 18*66; i += 256) {
                int r = i / 66, c = i % 66;
                int ih = ih0 + r, iw = c - 1;
                float v = ((unsigned)ih < 64u && (unsigned)iw < 64u) ? ip[ih*64+iw] : 0.0f;
                if (RELU_IN) v = fmaxf(v, 0.0f);
                sb[i] = v;
            }
        }
        const float* sb = s_in[ci&1];
        float iv[18];
#pragma unroll
        for (int r = 0; r < 6; ++r)
#pragma unroll
            for (int c = 0; c < 3; ++c)
                iv[r*3+c] = sb[(ty*4+r)*66 + tx + c];
        const float* wp = s_w + ci*72;
#pragma unroll
        for (int o = 0; o < 8; ++o) {
            float w0=wp[o*9+0],w1=wp[o*9+1],w2=wp[o*9+2],w3=wp[o*9+3],w4=wp[o*9+4],
                  w5=wp[o*9+5],w6=wp[o*9+6],w7=wp[o*9+7],w8=wp[o*9+8];
#pragma unroll
            for (int j = 0; j < 4; ++j) {
                float a = acc[j*8+o];
                a = fmaf(iv[(j+0)*3+0], w0, a);
                a = fmaf(iv[(j+0)*3+1], w1, a);
                a = fmaf(iv[(j+0)*3+2], w2, a);
                a = fmaf(iv[(j+1)*3+0], w3, a);
                a = fmaf(iv[(j+1)*3+1], w4, a);
                a = fmaf(iv[(j+1)*3+2], w5, a);
                a = fmaf(iv[(j+2)*3+0], w6, a);
                a = fmaf(iv[(j+2)*3+1], w7, a);
                a = fmaf(iv[(j+2)*3+2], w8, a);
                acc[j*8+o] = a;
            }
        }
        __syncthreads();
    }

    const int ohb = tile*16 + ty*4;
#pragma unroll
    for (int j = 0; j < 4; ++j)
#pragma unroll
        for (int o = 0; o < 8; ++o) {
            float v = acc[j*8+o];
            if (RELU_OUT) v = fmaxf(v, 0.0f);
            out[(((size_t)n * COUT + ocg*8+o) * 64 + ohb + j) * 64 + tx] = v;
        }
}

// ============ 4x4 s2 p1 conv, 64ch 128x128 -> 128ch 64x64 (ew2) ============
__global__ __launch_bounds__(256)
void conv4s2_t(const float* __restrict__ in, const float* __restrict__ w,
               const float* __restrict__ bias, float* __restrict__ out)
{
    __shared__ float s_in[2][34*130];
    __shared__ float s_wc[2][128];
    const int tid = threadIdx.x;
    const int tx = tid & 63, ty = tid >> 6;
    const int tile = blockIdx.x, n = blockIdx.y, ocg = blockIdx.z;
    const int ih0 = 32*tile - 1;
    const float* inN = in + (size_t)n * 64 * 16384;

    { // stage ci 0
        for (int i = tid; i < 34*130; i += 256) {
            int r = i / 130, c = i % 130;
            int ih = ih0 + r, iw = c - 1;
            s_in[0][i] = ((unsigned)ih < 128u && (unsigned)iw < 128u) ? inN[ih*128+iw] : 0.0f;
        }
        if (tid < 128)
            s_wc[0][tid] = w[((size_t)(ocg*8 + (tid>>4)) * 64 + 0) * 16 + (tid&15)];
    }
    __syncthreads();

    float acc[32];
#pragma unroll
    for (int o = 0; o < 8; ++o) {
        float b0 = __ldg(&bias[ocg*8+o]);
#pragma unroll
        for (int j = 0; j < 4; ++j) acc[j*8+o] = b0;
    }

#pragma unroll 1
    for (int ci = 0; ci < 64; ++ci) {
        if (ci + 1 < 64) {
            const float* ip = inN + (size_t)(ci+1) * 16384;
            float* sb = s_in[(ci+1)&1];
            for (int i = tid; i < 34*130; i += 256) {
                int r = i / 130, c = i % 130;
                int ih = ih0 + r, iw = c - 1;
                sb[i] = ((unsigned)ih < 128u && (unsigned)iw < 128u) ? ip[ih*128+iw] : 0.0f;
            }
            if (tid < 128)
                s_wc[(ci+1)&1][tid] = w[((size_t)(ocg*8 + (tid>>4)) * 64 + ci+1) * 16 + (tid&15)];
        }
        const float* sb = s_in[ci&1];
        const float* wc = s_wc[ci&1];
#pragma unroll
        for (int kh = 0; kh < 4; ++kh) {
            float iv[16];
#pragma unroll
            for (int j = 0; j < 4; ++j)
#pragma unroll
                for (int kw = 0; kw < 4; ++kw)
                    iv[j*4+kw] = sb[(2*(ty*4+j)+kh)*130 + 2*tx + kw];
#pragma unroll
            for (int o = 0; o < 8; ++o) {
                float v0 = wc[o*16+kh*4+0], v1 = wc[o*16+kh*4+1],
                      v2 = wc[o*16+kh*4+2], v3 = wc[o*16+kh*4+3];
#pragma unroll
                for (int j = 0; j < 4; ++j) {
                    float a = acc[j*8+o];
                    a = fmaf(iv[j*4+0], v0, a);
                    a = fmaf(iv[j*4+1], v1, a);
                    a = fmaf(iv[j*4+2], v2, a);
                    a = fmaf(iv[j*4+3], v3, a);
                    acc[j*8+o] = a;
                }
            }
        }
        __syncthreads();
    }

    const int ohb = tile*16 + ty*4;
#pragma unroll
    for (int j = 0; j < 4; ++j)
#pragma unroll
        for (int o = 0; o < 8; ++o)
            out[(((size_t)n * 128 + ocg*8+o) * 64 + ohb + j) * 64 + tx] = fmaxf(acc[j*8+o], 0.0f);
}

// ============ 4x4 s2 p1 conv, 1ch 256x256 -> 64ch 128x128 (ew1) ============
__global__ __launch_bounds__(256)
void ew1_t(const float* __restrict__ in, const float* __restrict__ w,
           const float* __restrict__ bias, float* __restrict__ out)
{
    __shared__ float s_in[34*130];
    __shared__ float s_w[128];
    const int tid = threadIdx.x;
    const int tx = tid & 63, ty = tid >> 6;
    const int rt = blockIdx.x >> 1, ct = blockIdx.x & 1;
    const int n = blockIdx.y, ocg = blockIdx.z;
    const int ih0 = 32*rt - 1, iw0 = 128*ct - 1;
    const float* ip = in + (size_t)n * 65536;

    for (int i = tid; i < 34*130; i += 256) {
        int r = i / 130, c = i % 130;
        int ih = ih0 + r, iw = iw0 + c;
        s_in[i] = ((unsigned)ih < 256u && (unsigned)iw < 256u) ? ip[ih*256+iw] : 0.0f;
    }
    if (tid < 128) s_w[tid] = w[(ocg*8 + (tid>>4))*16 + (tid&15)];
    __syncthreads();

    float acc[32];
#pragma unroll
    for (int o = 0; o < 8; ++o) {
        float b0 = __ldg(&bias[ocg*8+o]);
#pragma unroll
        for (int j = 0; j < 4; ++j) acc[j*8+o] = b0;
    }
#pragma unroll
    for (int kh = 0; kh < 4; ++kh) {
        float iv[16];
#pragma unroll
        for (int j = 0; j < 4; ++j)
#pragma unroll
            for (int kw = 0; kw < 4; ++kw)
                iv[j*4+kw] = s_in[(2*(ty*4+j)+kh)*130 + 2*tx + kw];
#pragma unroll
        for (int o = 0; o < 8; ++o) {
            float v0 = s_w[o*16+kh*4+0], v1 = s_w[o*16+kh*4+1],
                  v2 = s_w[o*16+kh*4+2], v3 = s_w[o*16+kh*4+3];
#pragma unroll
            for (int j = 0; j < 4; ++j) {
                float a = acc[j*8+o];
                a = fmaf(iv[j*4+0], v0, a);
                a = fmaf(iv[j*4+1], v1, a);
                a = fmaf(iv[j*4+2], v2, a);
                a = fmaf(iv[j*4+3], v3, a);
                acc[j*8+o] = a;
            }
        }
    }
    const int ohb = rt*16 + ty*4;
#pragma unroll
    for (int j = 0; j < 4; ++j)
#pragma unroll
        for (int o = 0; o < 8; ++o)
            out[(((size_t)n * 64 + ocg*8+o) * 128 + ohb + j) * 128 + ct*64 + tx] = fmaxf(acc[j*8+o], 0.0f);
}

// ============ convT 4x4 s2 p1, 128ch 64x64 -> 64ch 128x128 (dtw1) ============
// parity-class form: per out row r-pair taps; thread = 4 class rows x both px x 4 oc
__global__ __launch_bounds__(256)
void convT1_t(const float* __restrict__ in, const float* __restrict__ w,
              const float* __restrict__ bias, float* __restrict__ out)
{
    __shared__ float s_in[2][18*66];
    __shared__ float s_w[128*32];
    const int tid = threadIdx.x;
    const int tx = tid & 63, ty = tid >> 6;
    const int tile = blockIdx.x, n = blockIdx.y;
    const int py = blockIdx.z & 1, ocg = blockIdx.z >> 1;

    for (int i = tid; i < 128*32; i += 256) {
        int ci = i >> 5, rem = i & 31, o = rem >> 3, a = (rem >> 2) & 1, kw = rem & 3;
        int kh = py ? (a ? 0 : 2) : (a ? 1 : 3);
        s_w[i] = w[((size_t)ci * 64 + ocg*4 + o) * 16 + kh*4 + kw];
    }
    const int ih0 = tile*16 - 1;
    const float* inN = in + (size_t)n * 128 * 4096;

    for (int i = tid; i < 18*66; i += 256) {
        int r = i / 66, c = i % 66;
        int ih = ih0 + r, iw = c - 1;
        s_in[0][i] = ((unsigned)ih < 64u && (unsigned)iw < 64u) ? inN[ih*64+iw] : 0.0f;
    }
    __syncthreads();

    float acc[32]; // (j*2+px)*4+o
#pragma unroll
    for (int o = 0; o < 4; ++o) {
        float b0 = __ldg(&bias[ocg*4+o]);
#pragma unroll
        for (int jp = 0; jp < 8; ++jp) acc[jp*4+o] = b0;
    }

#pragma unroll 1
    for (int ci = 0; ci < 128; ++ci) {
        if (ci + 1 < 128) {
            const float* ip = inN + (size_t)(ci+1) * 4096;
            float* sb = s_in[(ci+1)&1];
            for (int i = tid; i < 18*66; i += 256) {
                int r = i / 66, c = i % 66;
                int ih = ih0 + r, iw = c - 1;
                sb[i] = ((unsigned)ih < 64u && (unsigned)iw < 64u) ? ip[ih*64+iw] : 0.0f;
            }
        }
        const float* sb = s_in[ci&1];
        const int rb = ty*4 + py;
        float iv[15];
#pragma unroll
        for (int r = 0; r < 5; ++r)
#pragma unroll
            for (int c = 0; c < 3; ++c)
                iv[r*3+c] = sb[(rb+r)*66 + tx + c];
        const float* wp = s_w + ci*32;
#pragma unroll
        for (int o = 0; o < 4; ++o) {
            float l0=wp[o*8+0],l1=wp[o*8+1],l2=wp[o*8+2],l3=wp[o*8+3];
            float h0=wp[o*8+4],h1=wp[o*8+5],h2=wp[o*8+6],h3=wp[o*8+7];
#pragma unroll
            for (int j = 0; j < 4; ++j) {
                float a0 = acc[(j*2+0)*4+o];
                a0 = fmaf(iv[j*3+0],     l3, a0);
                a0 = fmaf(iv[j*3+1],     l1, a0);
                a0 = fmaf(iv[(j+1)*3+0], h3, a0);
                a0 = fmaf(iv[(j+1)*3+1], h1, a0);
                acc[(j*2+0)*4+o] = a0;
                float a1 = acc[(j*2+1)*4+o];
                a1 = fmaf(iv[j*3+1],     l2, a1);
                a1 = fmaf(iv[j*3+2],     l0, a1);
                a1 = fmaf(iv[(j+1)*3+1], h2, a1);
                a1 = fmaf(iv[(j+1)*3+2], h0, a1);
                acc[(j*2+1)*4+o] = a1;
            }
        }
        __syncthreads();
    }

#pragma unroll
    for (int j = 0; j < 4; ++j) {
        int oh = 2*(tile*16 + ty*4 + j) + py;
#pragma unroll
        for (int o = 0; o < 4; ++o) {
            float2 v;
            v.x = fmaxf(acc[(j*2+0)*4+o], 0.0f);
            v.y = fmaxf(acc[(j*2+1)*4+o], 0.0f);
            *(float2*)&out[(((size_t)n * 64 + ocg*4+o) * 128 + oh) * 128 + 2*tx] = v;
        }
    }
}

// ============ convT 4x4 s2 p1, 64ch 128x128 -> 1ch 256x256 (dtw2) ============
__global__ __launch_bounds__(256)
void convT2_t(const float* __restrict__ in, const float* __restrict__ w,
              const float* __restrict__ bias, float* __restrict__ out)
{
    __shared__ float s_in[2][18*130];
    __shared__ float s_w[64*8];
    const int tid = threadIdx.x;
    const int tx = tid & 127, ty = tid >> 7;
    const int tile = blockIdx.x, n = blockIdx.y, py = blockIdx.z;

    for (int i = tid; i < 64*8; i += 256) {
        int ci = i >> 3, a = (i >> 2) & 1, kw = i & 3;
        int kh = py ? (a ? 0 : 2) : (a ? 1 : 3);
        s_w[i] = w[(size_t)ci * 16 + kh*4 + kw];
    }
    const int ih0 = tile*16 - 1;
    const float* inN = in + (size_t)n * 64 * 16384;

    for (int i = tid; i < 18*130; i += 256) {
        int r = i / 130, c = i % 130;
        int ih = ih0 + r, iw = c - 1;
        s_in[0][i] = ((unsigned)ih < 128u && (unsigned)iw < 128u) ? inN[ih*128+iw] : 0.0f;
    }
    __syncthreads();

    float b0 = __ldg(&bias[0]);
    float acc[16];
#pragma unroll
    for (int i = 0; i < 16; ++i) acc[i] = b0;

#pragma unroll 1
    for (int ci = 0; ci < 64; ++ci) {
        if (ci + 1 < 64) {
            const float* ip = inN + (size_t)(ci+1) * 16384;
            float* sb = s_in[(ci+1)&1];
            for (int i = tid; i < 18*130; i += 256) {
                int r = i / 130, c = i % 130;
                int ih = ih0 + r, iw = c - 1;
                sb[i] = ((unsigned)ih < 128u && (unsigned)iw < 128u) ? ip[ih*128+iw] : 0.0f;
            }
        }
        const float* sb = s_in[ci&1];
        const int rb = ty*8 + py;
        float iv[27];
#pragma unroll
        for (int r = 0; r < 9; ++r)
#pragma unroll
            for (int c = 0; c < 3; ++c)
                iv[r*3+c] = sb[(rb+r)*130 + tx + c];
        const float* wp = s_w + ci*8;
        float l0=wp[0],l1=wp[1],l2=wp[2],l3=wp[3],h0=wp[4],h1=wp[5],h2=wp[6],h3=wp[7];
#pragma unroll
        for (int j = 0; j < 8; ++j) {
            float a0 = acc[j*2+0];
            a0 = fmaf(iv[j*3+0],     l3, a0);
            a0 = fmaf(iv[j*3+1],     l1, a0);
            a0 = fmaf(iv[(j+1)*3+0], h3, a0);
            a0 = fmaf(iv[(j+1)*3+1], h1, a0);
            acc[j*2+0] = a0;
            float a1 = acc[j*2+1];
            a1 = fmaf(iv[j*3+1],     l2, a1);
            a1 = fmaf(iv[j*3+2],     l0, a1);
            a1 = fmaf(iv[(j+1)*3+1], h2, a1);
            a1 = fmaf(iv[(j+1)*3+2], h0, a1);
            acc[j*2+1] = a1;
        }
        __syncthreads();
    }

#pragma unroll
    for (int j = 0; j < 8; ++j) {
        int oh = 2*(tile*16 + ty*8 + j) + py;
        size_t base = (size_t)n * 65536 + (size_t)oh * 256 + 2*tx;
        out[base]     = acc[j*2+0];
        out[base + 1] = acc[j*2+1];
    }
}

// ============ 1x1 conv; thread = 1 px x 8 oc ============
template<int CIN, bool RELU_IN, bool HAS_BIAS, bool ADD_RES>
__global__ __launch_bounds__(256)
void conv1x1_t(const float* __restrict__ in, const float* __restrict__ w,
               const float* __restrict__ bias, const float* __restrict__ res,
               float* __restrict__ out, int COUT)
{
    __shared__ float s_w[CIN*8];
    const int tid = threadIdx.x;
    const int n = blockIdx.y, ocg = blockIdx.z;
    for (int i = tid; i < CIN*8; i += 256)
        s_w[i] = w[(size_t)(ocg*8 + (i&7)) * CIN + (i>>3)];
    __syncthreads();

    const int hw = blockIdx.x*256 + tid;
    float acc[8];
#pragma unroll
    for (int o = 0; o < 8; ++o) acc[o] = HAS_BIAS ? __ldg(&bias[ocg*8+o]) : 0.0f;
    const float* ip = in + ((size_t)n * CIN << 12) + hw;
#pragma unroll 8
    for (int ci = 0; ci < CIN; ++ci) {
        float v = ip[(size_t)ci << 12];
        if (RELU_IN) v = fmaxf(v, 0.0f);
#pragma unroll
        for (int o = 0; o < 8; ++o) acc[o] = fmaf(v, s_w[ci*8+o], acc[o]);
    }
#pragma unroll
    for (int o = 0; o < 8; ++o) {
        size_t oi = (((size_t)n * COUT + ocg*8+o) << 12) + hw;
        float v = acc[o];
        if (ADD_RES) v += res[oi];
        out[oi] = v;
    }
}

// ---------------- VQ (unchanged from passing R2) ----------------
__global__ void vq_prep(const float* __restrict__ cb)
{
    int k = blockIdx.x * blockDim.x + threadIdx.x;
    if (k < 512) {
        float s = 0.0f;
        const float* c = cb + k * 64;
#pragma unroll
        for (int d = 0; d < 64; ++d) s = fmaf(c[d], c[d], s);
        g_c2[k] = s;
        g_counts[k] = 0;
    }
}

__global__ void vq_argmin(const float* __restrict__ cb)
{
    __shared__ float sc[64 * 64];
    __shared__ float sc2[64];
    __shared__ int   hist[512];
    int tid = threadIdx.x;
    for (int i = tid; i < 512; i += 256) hist[i] = 0;

    int r  = blockIdx.x * 256 + tid;
    int n  = r >> 12;
    int hw = r & 4095;
    const float* zp = g_z + (size_t)n * 64 * 4096 + hw;

    float zr[64];
#pragma unroll
    for (int d = 0; d < 64; ++d) zr[d] = zp[(size_t)d * 4096];

    float z2 = 0.0f;
#pragma unroll
    for (int d = 0; d < 64; ++d) z2 = fmaf(zr[d], zr[d], z2);

    float best = 3.4e38f;
    int bi = 0;
    for (int chunk = 0; chunk < 8; ++chunk) {
        __syncthreads();
        for (int i = tid; i < 4096; i += 256) sc[i] = cb[chunk * 4096 + i];
        if (tid < 64) sc2[tid] = g_c2[chunk * 64 + tid];
        __syncthreads();
        for (int c = 0; c < 64; ++c) {
            const float4* cv = (const float4*)&sc[c * 64];
            float d0 = 0, d1 = 0, d2 = 0, d3 = 0;
#pragma unroll
            for (int j = 0; j < 16; ++j) {
                float4 v = cv[j];
                d0 = fmaf(v.x, zr[4 * j + 0], d0);
                d1 = fmaf(v.y, zr[4 * j + 1], d1);
                d2 = fmaf(v.z, zr[4 * j + 2], d2);
                d3 = fmaf(v.w, zr[4 * j + 3], d3);
            }
            float dot = (d0 + d1) + (d2 + d3);
            float dist = __fadd_rn(__fadd_rn(z2, sc2[c]), -2.0f * dot);
            if (dist < best) { best = dist; bi = chunk * 64 + c; }
        }
    }
    g_idx[r] = bi;
    atomicAdd(&hist[bi], 1);
    __syncthreads();
    for (int i = tid; i < 512; i += 256)
        if (hist[i]) atomicAdd(&g_counts[i], hist[i]);
}

__global__ void fill_zero2(float2* __restrict__ p, int n2)
{
    int i = blockIdx.x * blockDim.x + threadIdx.x;
    if (i < n2) p[i] = make_float2(0.0f, 0.0f);
}

__global__ void vq_quant(const float* __restrict__ cb, float* __restrict__ out_enc,
                         float* __restrict__ out_quant)
{
    __shared__ float red[256];
    int tid = threadIdx.x;
    int r   = blockIdx.x * 256 + tid;
    int k   = g_idx[r];
    int n   = r >> 12;
    int hw  = r & 4095;
    size_t base = (size_t)n * 64 * 4096 + hw;
    const float* zp = g_z + base;
    float* qp = g_q + base;
    float* oq = out_quant + base;
    const float* ck = cb + k * 64;

    float sse = 0.0f;
#pragma unroll
    for (int d = 0; d < 64; ++d) {
        float qv = __ldg(&ck[d]);
        float zv = zp[(size_t)d * 4096];
        qp[(size_t)d * 4096] = qv;
        oq[(size_t)d * 4096] = qv;
        float df = qv - zv;
        sse = fmaf(df, df, sse);
    }
    out_enc[(size_t)r * 512 + k] = 1.0f;

    red[tid] = sse;
    __syncthreads();
    for (int s = 128; s > 0; s >>= 1) {
        if (tid < s) red[tid] += red[tid + s];
        __syncthreads();
    }
    if (tid == 0) g_partial[blockIdx.x] = red[0];
}

__global__ void vq_final(float* __restrict__ d_out)
{
    __shared__ float sh[512];
    int t = threadIdx.x;
    float avg = (float)g_counts[t] * (1.0f / 65536.0f);
    sh[t] = avg * logf(avg + 1e-10f);
    __syncthreads();
    for (int s = 256; s > 0; s >>= 1) {
        if (t < s) sh[t] += sh[t + s];
        __syncthreads();
    }
    if (t == 0) {
        d_out[OFF_PERP] = expf(-sh[0]);
        double acc = 0.0;
        for (int i = 0; i < 256; ++i) acc += (double)g_partial[i];
        d_out[0] = (float)(1.25 * acc / (65536.0 * 64.0));
    }
}

// ---------------- host launcher ----------------
static inline int grd(long long total) { return (int)((total + 255) / 256); }

extern "C" void kernel_launch(void* const* d_in, const int* in_sizes, int n_in,
                              void* d_out_v, int out_size)
{
    const float* x    = (const float*)d_in[0];
    const float* ew1  = (const float*)d_in[1];
    const float* eb1  = (const float*)d_in[2];
    const float* ew2  = (const float*)d_in[3];
    const float* eb2  = (const float*)d_in[4];
    const float* ew3  = (const float*)d_in[5];
    const float* eb3  = (const float*)d_in[6];
    const float* er1a = (const float*)d_in[7];
    const float* er1b = (const float*)d_in[8];
    const float* er2a = (const float*)d_in[9];
    const float* er2b = (const float*)d_in[10];
    const float* pwW  = (const float*)d_in[11];
    const float* pb   = (const float*)d_in[12];
    const float* cb   = (const float*)d_in[13];
    const float* dw1  = (const float*)d_in[14];
    const float* db1  = (const float*)d_in[15];
    const float* dr1a = (const float*)d_in[16];
    const float* dr1b = (const float*)d_in[17];
    const float* dr2a = (const float*)d_in[18];
    const float* dr2b = (const float*)d_in[19];
    const float* dtw1 = (const float*)d_in[20];
    const float* dtb1 = (const float*)d_in[21];
    const float* dtw2 = (const float*)d_in[22];
    const float* dtb2 = (const float*)d_in[23];
    float* d_out = (float*)d_out_v;

    void* p;
    float *h1, *a, *b, *c, *z, *q;
    cudaGetSymbolAddress(&p, g_h1); h1 = (float*)p;
    cudaGetSymbolAddress(&p, g_a);  a  = (float*)p;
    cudaGetSymbolAddress(&p, g_b);  b  = (float*)p;
    cudaGetSymbolAddress(&p, g_c);  c  = (float*)p;
    cudaGetSymbolAddress(&p, g_z);  z  = (float*)p;
    cudaGetSymbolAddress(&p, g_q);  q  = (float*)p;

    // ---- encoder ----
    ew1_t<<<dim3(16,16,8), 256>>>(x, ew1, eb1, h1);
    conv4s2_t<<<dim3(4,16,16), 256>>>(h1, ew2, eb2, a);
    conv3_t<128,false,false,true><<<dim3(4,16,16), 256>>>(a, ew3, eb3, b, 128);
    conv3_t<128,true, false,false><<<dim3(4,16,4), 256>>>(b, er1a, nullptr, c, 32);
    conv1x1_t<32,true,false,true><<<dim3(16,16,16), 256>>>(c, er1b, nullptr, b, a, 128);
    conv3_t<128,true, false,false><<<dim3(4,16,4), 256>>>(a, er2a, nullptr, c, 32);
    conv1x1_t<32,true,false,true><<<dim3(16,16,16), 256>>>(c, er2b, nullptr, a, b, 128);
    conv1x1_t<128,true,true,false><<<dim3(16,16,8), 256>>>(b, pwW, pb, nullptr, z, 64);

    // ---- vector quantizer ----
    vq_prep<<<2, 256>>>(cb);
    vq_argmin<<<256, 256>>>(cb);
    fill_zero2<<<grd(16777216), 256>>>((float2*)(d_out + OFF_ENC), 16777216);
    vq_quant<<<256, 256>>>(cb, d_out + OFF_ENC, d_out + OFF_QUANT);
    vq_final<<<1, 512>>>(d_out);

    // ---- decoder ----
    conv3_t<64,false,false,true><<<dim3(4,16,16), 256>>>(q, dw1, db1, a, 128);
    conv3_t<128,true,false,false><<<dim3(4,16,4), 256>>>(a, dr1a, nullptr, c, 32);
    conv1x1_t<32,true,false,true><<<dim3(16,16,16), 256>>>(c, dr1b, nullptr, a, b, 128);
    conv3_t<128,true,false,false><<<dim3(4,16,4), 256>>>(b, dr2a, nullptr, c, 32);
    conv1x1_t<32,true,false,true><<<dim3(16,16,16), 256>>>(c, dr2b, nullptr, b, a, 128);
    convT1_t<<<dim3(4,16,32), 256>>>(a, dtw1, dtb1, h1);
    convT2_t<<<dim3(8,16,2), 256>>>(h1, dtw2, dtb2, d_out + OFF_XREC);
}

// round 5
// speedup vs baseline: 3.6214x; 1.1593x over previous
#include <cuda_runtime.h>
#include <math.h>

// ---------------- static device scratch ----------------
__device__ float g_h1[(size_t)16*64*128*128];
__device__ float g_a [(size_t)16*128*64*64];
__device__ float g_b [(size_t)16*128*64*64];
__device__ float g_c [(size_t)16*32*64*64];
__device__ float g_z [(size_t)16*64*64*64];
__device__ float g_q [(size_t)16*64*64*64];
__device__ int   g_idx[65536];
__device__ float g_c2[512];
__device__ int   g_counts[512];
__device__ float g_partial[256];

#define OFF_XREC   1
#define OFF_PERP   1048577
#define OFF_ENC    1048578
#define OFF_QUANT  34603010

// ============ 3x3 s1 p1 conv on 64x64; 8-row tile; thread = 2 rows x 8 oc ============
template<int CIN, bool RELU_IN, bool RELU_OUT, bool HAS_BIAS>
__global__ __launch_bounds__(256)
void conv3_t(const float* __restrict__ in, const float* __restrict__ w,
             const float* __restrict__ bias, float* __restrict__ out, int COUT)
{
    __shared__ float s_in[2][10*66];
    __shared__ float s_w[CIN*72];
    const int tid = threadIdx.x;
    const int tx = tid & 63, ty = tid >> 6;
    const int tile = blockIdx.x, n = blockIdx.y, ocg = blockIdx.z;

    for (int i = tid; i < CIN*72; i += 256) {
        int ci = i / 72, rem = i % 72, o = rem / 9, t = rem % 9;
        s_w[i] = w[((size_t)(ocg*8 + o) * CIN + ci) * 9 + t];
    }
    const int ih0 = tile*8 - 1;
    const float* inN = in + (size_t)n * CIN * 4096;

    for (int i = tid; i < 10*66; i += 256) {
        int r = i / 66, c = i % 66;
        int ih = ih0 + r, iw = c - 1;
        float v = ((unsigned)ih < 64u && (unsigned)iw < 64u) ? inN[ih*64+iw] : 0.0f;
        if (RELU_IN) v = fmaxf(v, 0.0f);
        s_in[0][i] = v;
    }
    __syncthreads();

    float acc[16];
#pragma unroll
    for (int o = 0; o < 8; ++o) {
        float b0 = HAS_BIAS ? __ldg(&bias[ocg*8+o]) : 0.0f;
        acc[o] = b0; acc[8+o] = b0;
    }

#pragma unroll 1
    for (int ci = 0; ci < CIN; ++ci) {
        if (ci + 1 < CIN) {
            const float* ip = inN + (size_t)(ci+1) * 4096;
            float* sb = s_in[(ci+1)&1];
            for (int i = tid; i < 10*66; i += 256) {
                int r = i / 66, c = i % 66;
                int ih = ih0 + r, iw = c - 1;
                float v = ((unsigned)ih < 64u && (unsigned)iw < 64u) ? ip[ih*64+iw] : 0.0f;
                if (RELU_IN) v = fmaxf(v, 0.0f);
                sb[i] = v;
            }
        }
        const float* sb = s_in[ci&1];
        float iv[12];
#pragma unroll
        for (int r = 0; r < 4; ++r)
#pragma unroll
            for (int c = 0; c < 3; ++c)
                iv[r*3+c] = sb[(ty*2+r)*66 + tx + c];
        const float* wp = s_w + ci*72;
#pragma unroll
        for (int o = 0; o < 8; ++o) {
            float w0=wp[o*9+0],w1=wp[o*9+1],w2=wp[o*9+2],w3=wp[o*9+3],w4=wp[o*9+4],
                  w5=wp[o*9+5],w6=wp[o*9+6],w7=wp[o*9+7],w8=wp[o*9+8];
#pragma unroll
            for (int j = 0; j < 2; ++j) {
                float a = acc[j*8+o];
                a = fmaf(iv[(j+0)*3+0], w0, a);
                a = fmaf(iv[(j+0)*3+1], w1, a);
                a = fmaf(iv[(j+0)*3+2], w2, a);
                a = fmaf(iv[(j+1)*3+0], w3, a);
                a = fmaf(iv[(j+1)*3+1], w4, a);
                a = fmaf(iv[(j+1)*3+2], w5, a);
                a = fmaf(iv[(j+2)*3+0], w6, a);
                a = fmaf(iv[(j+2)*3+1], w7, a);
                a = fmaf(iv[(j+2)*3+2], w8, a);
                acc[j*8+o] = a;
            }
        }
        __syncthreads();
    }

    const int ohb = tile*8 + ty*2;
#pragma unroll
    for (int j = 0; j < 2; ++j)
#pragma unroll
        for (int o = 0; o < 8; ++o) {
            float v = acc[j*8+o];
            if (RELU_OUT) v = fmaxf(v, 0.0f);
            out[(((size_t)n * COUT + ocg*8+o) * 64 + ohb + j) * 64 + tx] = v;
        }
}

// ============ 4x4 s2 p1 conv, 64ch 128x128 -> 128ch 64x64 (ew2); 8-out-row tile ============
__global__ __launch_bounds__(256)
void conv4s2_t(const float* __restrict__ in, const float* __restrict__ w,
               const float* __restrict__ bias, float* __restrict__ out)
{
    __shared__ float s_in[2][18*130];
    __shared__ float s_wc[2][128];
    const int tid = threadIdx.x;
    const int tx = tid & 63, ty = tid >> 6;
    const int tile = blockIdx.x, n = blockIdx.y, ocg = blockIdx.z;
    const int ih0 = 16*tile - 1;
    const float* inN = in + (size_t)n * 64 * 16384;

    for (int i = tid; i < 18*130; i += 256) {
        int r = i / 130, c = i % 130;
        int ih = ih0 + r, iw = c - 1;
        s_in[0][i] = ((unsigned)ih < 128u && (unsigned)iw < 128u) ? inN[ih*128+iw] : 0.0f;
    }
    if (tid < 128)
        s_wc[0][tid] = w[((size_t)(ocg*8 + (tid>>4)) * 64 + 0) * 16 + (tid&15)];
    __syncthreads();

    float acc[16];
#pragma unroll
    for (int o = 0; o < 8; ++o) {
        float b0 = __ldg(&bias[ocg*8+o]);
        acc[o] = b0; acc[8+o] = b0;
    }

#pragma unroll 1
    for (int ci = 0; ci < 64; ++ci) {
        if (ci + 1 < 64) {
            const float* ip = inN + (size_t)(ci+1) * 16384;
            float* sb = s_in[(ci+1)&1];
            for (int i = tid; i < 18*130; i += 256) {
                int r = i / 130, c = i % 130;
                int ih = ih0 + r, iw = c - 1;
                sb[i] = ((unsigned)ih < 128u && (unsigned)iw < 128u) ? ip[ih*128+iw] : 0.0f;
            }
            if (tid < 128)
                s_wc[(ci+1)&1][tid] = w[((size_t)(ocg*8 + (tid>>4)) * 64 + ci+1) * 16 + (tid&15)];
        }
        const float* sb = s_in[ci&1];
        const float* wc = s_wc[ci&1];
#pragma unroll
        for (int kh = 0; kh < 4; ++kh) {
            float iv[8];
#pragma unroll
            for (int j = 0; j < 2; ++j)
#pragma unroll
                for (int kw = 0; kw < 4; ++kw)
                    iv[j*4+kw] = sb[(2*(ty*2+j)+kh)*130 + 2*tx + kw];
#pragma unroll
            for (int o = 0; o < 8; ++o) {
                float v0 = wc[o*16+kh*4+0], v1 = wc[o*16+kh*4+1],
                      v2 = wc[o*16+kh*4+2], v3 = wc[o*16+kh*4+3];
#pragma unroll
                for (int j = 0; j < 2; ++j) {
                    float a = acc[j*8+o];
                    a = fmaf(iv[j*4+0], v0, a);
                    a = fmaf(iv[j*4+1], v1, a);
                    a = fmaf(iv[j*4+2], v2, a);
                    a = fmaf(iv[j*4+3], v3, a);
                    acc[j*8+o] = a;
                }
            }
        }
        __syncthreads();
    }

    const int ohb = tile*8 + ty*2;
#pragma unroll
    for (int j = 0; j < 2; ++j)
#pragma unroll
        for (int o = 0; o < 8; ++o)
            out[(((size_t)n * 128 + ocg*8+o) * 64 + ohb + j) * 64 + tx] = fmaxf(acc[j*8+o], 0.0f);
}

// ============ 4x4 s2 p1 conv, 1ch 256x256 -> 64ch 128x128 (ew1) ============
__global__ __launch_bounds__(256)
void ew1_t(const float* __restrict__ in, const float* __restrict__ w,
           const float* __restrict__ bias, float* __restrict__ out)
{
    __shared__ float s_in[34*130];
    __shared__ float s_w[128];
    const int tid = threadIdx.x;
    const int tx = tid & 63, ty = tid >> 6;
    const int rt = blockIdx.x >> 1, ct = blockIdx.x & 1;
    const int n = blockIdx.y, ocg = blockIdx.z;
    const int ih0 = 32*rt - 1, iw0 = 128*ct - 1;
    const float* ip = in + (size_t)n * 65536;

    for (int i = tid; i < 34*130; i += 256) {
        int r = i / 130, c = i % 130;
        int ih = ih0 + r, iw = iw0 + c;
        s_in[i] = ((unsigned)ih < 256u && (unsigned)iw < 256u) ? ip[ih*256+iw] : 0.0f;
    }
    if (tid < 128) s_w[tid] = w[(ocg*8 + (tid>>4))*16 + (tid&15)];
    __syncthreads();

    float acc[32];
#pragma unroll
    for (int o = 0; o < 8; ++o) {
        float b0 = __ldg(&bias[ocg*8+o]);
#pragma unroll
        for (int j = 0; j < 4; ++j) acc[j*8+o] = b0;
    }
#pragma unroll
    for (int kh = 0; kh < 4; ++kh) {
        float iv[16];
#pragma unroll
        for (int j = 0; j < 4; ++j)
#pragma unroll
            for (int kw = 0; kw < 4; ++kw)
                iv[j*4+kw] = s_in[(2*(ty*4+j)+kh)*130 + 2*tx + kw];
#pragma unroll
        for (int o = 0; o < 8; ++o) {
            float v0 = s_w[o*16+kh*4+0], v1 = s_w[o*16+kh*4+1],
                  v2 = s_w[o*16+kh*4+2], v3 = s_w[o*16+kh*4+3];
#pragma unroll
            for (int j = 0; j < 4; ++j) {
                float a = acc[j*8+o];
                a = fmaf(iv[j*4+0], v0, a);
                a = fmaf(iv[j*4+1], v1, a);
                a = fmaf(iv[j*4+2], v2, a);
                a = fmaf(iv[j*4+3], v3, a);
                acc[j*8+o] = a;
            }
        }
    }
    const int ohb = rt*16 + ty*4;
#pragma unroll
    for (int j = 0; j < 4; ++j)
#pragma unroll
        for (int o = 0; o < 8; ++o)
            out[(((size_t)n * 64 + ocg*8+o) * 128 + ohb + j) * 128 + ct*64 + tx] = fmaxf(acc[j*8+o], 0.0f);
}

// ============ convT 4x4 s2 p1, 128ch 64x64 -> 64ch 128x128 (dtw1); 8-class-row tile ============
__global__ __launch_bounds__(256)
void convT1_t(const float* __restrict__ in, const float* __restrict__ w,
              const float* __restrict__ bias, float* __restrict__ out)
{
    __shared__ float s_in[2][10*66];
    __shared__ float s_w[128*32];
    const int tid = threadIdx.x;
    const int tx = tid & 63, ty = tid >> 6;
    const int tile = blockIdx.x, n = blockIdx.y;
    const int py = blockIdx.z & 1, ocg = blockIdx.z >> 1;

    for (int i = tid; i < 128*32; i += 256) {
        int ci = i >> 5, rem = i & 31, o = rem >> 3, a = (rem >> 2) & 1, kw = rem & 3;
        int kh = py ? (a ? 0 : 2) : (a ? 1 : 3);
        s_w[i] = w[((size_t)ci * 64 + ocg*4 + o) * 16 + kh*4 + kw];
    }
    const int ih0 = tile*8 - 1;
    const float* inN = in + (size_t)n * 128 * 4096;

    for (int i = tid; i < 10*66; i += 256) {
        int r = i / 66, c = i % 66;
        int ih = ih0 + r, iw = c - 1;
        s_in[0][i] = ((unsigned)ih < 64u && (unsigned)iw < 64u) ? inN[ih*64+iw] : 0.0f;
    }
    __syncthreads();

    float acc[16]; // (j*2+px)*4+o, j 0..1
#pragma unroll
    for (int o = 0; o < 4; ++o) {
        float b0 = __ldg(&bias[ocg*4+o]);
#pragma unroll
        for (int jp = 0; jp < 4; ++jp) acc[jp*4+o] = b0;
    }

#pragma unroll 1
    for (int ci = 0; ci < 128; ++ci) {
        if (ci + 1 < 128) {
            const float* ip = inN + (size_t)(ci+1) * 4096;
            float* sb = s_in[(ci+1)&1];
            for (int i = tid; i < 10*66; i += 256) {
                int r = i / 66, c = i % 66;
                int ih = ih0 + r, iw = c - 1;
                sb[i] = ((unsigned)ih < 64u && (unsigned)iw < 64u) ? ip[ih*64+iw] : 0.0f;
            }
        }
        const float* sb = s_in[ci&1];
        const int rb = ty*2 + py;
        float iv[9];
#pragma unroll
        for (int r = 0; r < 3; ++r)
#pragma unroll
            for (int c = 0; c < 3; ++c)
                iv[r*3+c] = sb[(rb+r)*66 + tx + c];
        const float* wp = s_w + ci*32;
#pragma unroll
        for (int o = 0; o < 4; ++o) {
            float l0=wp[o*8+0],l1=wp[o*8+1],l2=wp[o*8+2],l3=wp[o*8+3];
            float h0=wp[o*8+4],h1=wp[o*8+5],h2=wp[o*8+6],h3=wp[o*8+7];
#pragma unroll
            for (int j = 0; j < 2; ++j) {
                float a0 = acc[(j*2+0)*4+o];
                a0 = fmaf(iv[j*3+0],     l3, a0);
                a0 = fmaf(iv[j*3+1],     l1, a0);
                a0 = fmaf(iv[(j+1)*3+0], h3, a0);
                a0 = fmaf(iv[(j+1)*3+1], h1, a0);
                acc[(j*2+0)*4+o] = a0;
                float a1 = acc[(j*2+1)*4+o];
                a1 = fmaf(iv[j*3+1],     l2, a1);
                a1 = fmaf(iv[j*3+2],     l0, a1);
                a1 = fmaf(iv[(j+1)*3+1], h2, a1);
                a1 = fmaf(iv[(j+1)*3+2], h0, a1);
                acc[(j*2+1)*4+o] = a1;
            }
        }
        __syncthreads();
    }

#pragma unroll
    for (int j = 0; j < 2; ++j) {
        int oh = 2*(tile*8 + ty*2 + j) + py;
#pragma unroll
        for (int o = 0; o < 4; ++o) {
            float2 v;
            v.x = fmaxf(acc[(j*2+0)*4+o], 0.0f);
            v.y = fmaxf(acc[(j*2+1)*4+o], 0.0f);
            *(float2*)&out[(((size_t)n * 64 + ocg*4+o) * 128 + oh) * 128 + 2*tx] = v;
        }
    }
}

// ============ convT 4x4 s2 p1, 64ch 128x128 -> 1ch 256x256 (dtw2); 8-class-row tile ============
__global__ __launch_bounds__(256)
void convT2_t(const float* __restrict__ in, const float* __restrict__ w,
              const float* __restrict__ bias, float* __restrict__ out)
{
    __shared__ float s_in[2][10*130];
    __shared__ float s_w[64*8];
    const int tid = threadIdx.x;
    const int tx = tid & 127, ty = tid >> 7;
    const int tile = blockIdx.x, n = blockIdx.y, py = blockIdx.z;

    for (int i = tid; i < 64*8; i += 256) {
        int ci = i >> 3, a = (i >> 2) & 1, kw = i & 3;
        int kh = py ? (a ? 0 : 2) : (a ? 1 : 3);
        s_w[i] = w[(size_t)ci * 16 + kh*4 + kw];
    }
    const int ih0 = tile*8 - 1;
    const float* inN = in + (size_t)n * 64 * 16384;

    for (int i = tid; i < 10*130; i += 256) {
        int r = i / 130, c = i % 130;
        int ih = ih0 + r, iw = c - 1;
        s_in[0][i] = ((unsigned)ih < 128u && (unsigned)iw < 128u) ? inN[ih*128+iw] : 0.0f;
    }
    __syncthreads();

    float b0 = __ldg(&bias[0]);
    float acc[8];
#pragma unroll
    for (int i = 0; i < 8; ++i) acc[i] = b0;

#pragma unroll 1
    for (int ci = 0; ci < 64; ++ci) {
        if (ci + 1 < 64) {
            const float* ip = inN + (size_t)(ci+1) * 16384;
            float* sb = s_in[(ci+1)&1];
            for (int i = tid; i < 10*130; i += 256) {
                int r = i / 130, c = i % 130;
                int ih = ih0 + r, iw = c - 1;
                sb[i] = ((unsigned)ih < 128u && (unsigned)iw < 128u) ? ip[ih*128+iw] : 0.0f;
            }
        }
        const float* sb = s_in[ci&1];
        const int rb = ty*4 + py;
        float iv[15];
#pragma unroll
        for (int r = 0; r < 5; ++r)
#pragma unroll
            for (int c = 0; c < 3; ++c)
                iv[r*3+c] = sb[(rb+r)*130 + tx + c];
        const float* wp = s_w + ci*8;
        float l0=wp[0],l1=wp[1],l2=wp[2],l3=wp[3],h0=wp[4],h1=wp[5],h2=wp[6],h3=wp[7];
#pragma unroll
        for (int j = 0; j < 4; ++j) {
            float a0 = acc[j*2+0];
            a0 = fmaf(iv[j*3+0],     l3, a0);
            a0 = fmaf(iv[j*3+1],     l1, a0);
            a0 = fmaf(iv[(j+1)*3+0], h3, a0);
            a0 = fmaf(iv[(j+1)*3+1], h1, a0);
            acc[j*2+0] = a0;
            float a1 = acc[j*2+1];
            a1 = fmaf(iv[j*3+1],     l2, a1);
            a1 = fmaf(iv[j*3+2],     l0, a1);
            a1 = fmaf(iv[(j+1)*3+1], h2, a1);
            a1 = fmaf(iv[(j+1)*3+2], h0, a1);
            acc[j*2+1] = a1;
        }
        __syncthreads();
    }

#pragma unroll
    for (int j = 0; j < 4; ++j) {
        int oh = 2*(tile*8 + ty*4 + j) + py;
        size_t base = (size_t)n * 65536 + (size_t)oh * 256 + 2*tx;
        out[base]     = acc[j*2+0];
        out[base + 1] = acc[j*2+1];
    }
}

// ============ 1x1 conv; thread = 1 px x 16 oc ============
template<int CIN, bool RELU_IN, bool HAS_BIAS, bool ADD_RES>
__global__ __launch_bounds__(256)
void conv1x1_t(const float* __restrict__ in, const float* __restrict__ w,
               const float* __restrict__ bias, const float* __restrict__ res,
               float* __restrict__ out, int COUT)
{
    __shared__ float s_w[CIN*16];
    const int tid = threadIdx.x;
    const int n = blockIdx.y, ocg = blockIdx.z;
    for (int i = tid; i < CIN*16; i += 256)
        s_w[i] = w[(size_t)(ocg*16 + (i&15)) * CIN + (i>>4)];
    __syncthreads();

    const int hw = blockIdx.x*256 + tid;
    float acc[16];
#pragma unroll
    for (int o = 0; o < 16; ++o) acc[o] = HAS_BIAS ? __ldg(&bias[ocg*16+o]) : 0.0f;
    const float* ip = in + ((size_t)n * CIN << 12) + hw;
#pragma unroll 4
    for (int ci = 0; ci < CIN; ++ci) {
        float v = ip[(size_t)ci << 12];
        if (RELU_IN) v = fmaxf(v, 0.0f);
#pragma unroll
        for (int o = 0; o < 16; ++o) acc[o] = fmaf(v, s_w[ci*16+o], acc[o]);
    }
#pragma unroll
    for (int o = 0; o < 16; ++o) {
        size_t oi = (((size_t)n * COUT + ocg*16+o) << 12) + hw;
        float v = acc[o];
        if (ADD_RES) v += res[oi];
        out[oi] = v;
    }
}

// ---------------- VQ (unchanged, bit-exact tie-break) ----------------
__global__ void vq_prep(const float* __restrict__ cb)
{
    int k = blockIdx.x * blockDim.x + threadIdx.x;
    if (k < 512) {
        float s = 0.0f;
        const float* c = cb + k * 64;
#pragma unroll
        for (int d = 0; d < 64; ++d) s = fmaf(c[d], c[d], s);
        g_c2[k] = s;
        g_counts[k] = 0;
    }
}

__global__ void vq_argmin(const float* __restrict__ cb)
{
    __shared__ float sc[64 * 64];
    __shared__ float sc2[64];
    __shared__ int   hist[512];
    int tid = threadIdx.x;
    for (int i = tid; i < 512; i += 256) hist[i] = 0;

    int r  = blockIdx.x * 256 + tid;
    int n  = r >> 12;
    int hw = r & 4095;
    const float* zp = g_z + (size_t)n * 64 * 4096 + hw;

    float zr[64];
#pragma unroll
    for (int d = 0; d < 64; ++d) zr[d] = zp[(size_t)d * 4096];

    float z2 = 0.0f;
#pragma unroll
    for (int d = 0; d < 64; ++d) z2 = fmaf(zr[d], zr[d], z2);

    float best = 3.4e38f;
    int bi = 0;
    for (int chunk = 0; chunk < 8; ++chunk) {
        __syncthreads();
        for (int i = tid; i < 4096; i += 256) sc[i] = cb[chunk * 4096 + i];
        if (tid < 64) sc2[tid] = g_c2[chunk * 64 + tid];
        __syncthreads();
        for (int c = 0; c < 64; ++c) {
            const float4* cv = (const float4*)&sc[c * 64];
            float d0 = 0, d1 = 0, d2 = 0, d3 = 0;
#pragma unroll
            for (int j = 0; j < 16; ++j) {
                float4 v = cv[j];
                d0 = fmaf(v.x, zr[4 * j + 0], d0);
                d1 = fmaf(v.y, zr[4 * j + 1], d1);
                d2 = fmaf(v.z, zr[4 * j + 2], d2);
                d3 = fmaf(v.w, zr[4 * j + 3], d3);
            }
            float dot = (d0 + d1) + (d2 + d3);
            float dist = __fadd_rn(__fadd_rn(z2, sc2[c]), -2.0f * dot);
            if (dist < best) { best = dist; bi = chunk * 64 + c; }
        }
    }
    g_idx[r] = bi;
    atomicAdd(&hist[bi], 1);
    __syncthreads();
    for (int i = tid; i < 512; i += 256)
        if (hist[i]) atomicAdd(&g_counts[i], hist[i]);
}

__global__ void fill_zero2(float2* __restrict__ p, int n2)
{
    int i = blockIdx.x * blockDim.x + threadIdx.x;
    if (i < n2) p[i] = make_float2(0.0f, 0.0f);
}

__global__ void vq_quant(const float* __restrict__ cb, float* __restrict__ out_enc,
                         float* __restrict__ out_quant)
{
    __shared__ float red[256];
    int tid = threadIdx.x;
    int r   = blockIdx.x * 256 + tid;
    int k   = g_idx[r];
    int n   = r >> 12;
    int hw  = r & 4095;
    size_t base = (size_t)n * 64 * 4096 + hw;
    const float* zp = g_z + base;
    float* qp = g_q + base;
    float* oq = out_quant + base;
    const float* ck = cb + k * 64;

    float sse = 0.0f;
#pragma unroll
    for (int d = 0; d < 64; ++d) {
        float qv = __ldg(&ck[d]);
        float zv = zp[(size_t)d * 4096];
        qp[(size_t)d * 4096] = qv;
        oq[(size_t)d * 4096] = qv;
        float df = qv - zv;
        sse = fmaf(df, df, sse);
    }
    out_enc[(size_t)r * 512 + k] = 1.0f;

    red[tid] = sse;
    __syncthreads();
    for (int s = 128; s > 0; s >>= 1) {
        if (tid < s) red[tid] += red[tid + s];
        __syncthreads();
    }
    if (tid == 0) g_partial[blockIdx.x] = red[0];
}

__global__ void vq_final(float* __restrict__ d_out)
{
    __shared__ float sh[512];
    int t = threadIdx.x;
    float avg = (float)g_counts[t] * (1.0f / 65536.0f);
    sh[t] = avg * logf(avg + 1e-10f);
    __syncthreads();
    for (int s = 256; s > 0; s >>= 1) {
        if (t < s) sh[t] += sh[t + s];
        __syncthreads();
    }
    if (t == 0) {
        d_out[OFF_PERP] = expf(-sh[0]);
        double acc = 0.0;
        for (int i = 0; i < 256; ++i) acc += (double)g_partial[i];
        d_out[0] = (float)(1.25 * acc / (65536.0 * 64.0));
    }
}

// ---------------- host launcher ----------------
static inline int grd(long long total) { return (int)((total + 255) / 256); }

extern "C" void kernel_launch(void* const* d_in, const int* in_sizes, int n_in,
                              void* d_out_v, int out_size)
{
    const float* x    = (const float*)d_in[0];
    const float* ew1  = (const float*)d_in[1];
    const float* eb1  = (const float*)d_in[2];
    const float* ew2  = (const float*)d_in[3];
    const float* eb2  = (const float*)d_in[4];
    const float* ew3  = (const float*)d_in[5];
    const float* eb3  = (const float*)d_in[6];
    const float* er1a = (const float*)d_in[7];
    const float* er1b = (const float*)d_in[8];
    const float* er2a = (const float*)d_in[9];
    const float* er2b = (const float*)d_in[10];
    const float* pwW  = (const float*)d_in[11];
    const float* pb   = (const float*)d_in[12];
    const float* cb   = (const float*)d_in[13];
    const float* dw1  = (const float*)d_in[14];
    const float* db1  = (const float*)d_in[15];
    const float* dr1a = (const float*)d_in[16];
    const float* dr1b = (const float*)d_in[17];
    const float* dr2a = (const float*)d_in[18];
    const float* dr2b = (const float*)d_in[19];
    const float* dtw1 = (const float*)d_in[20];
    const float* dtb1 = (const float*)d_in[21];
    const float* dtw2 = (const float*)d_in[22];
    const float* dtb2 = (const float*)d_in[23];
    float* d_out = (float*)d_out_v;

    void* p;
    float *h1, *a, *b, *c, *z, *q;
    cudaGetSymbolAddress(&p, g_h1); h1 = (float*)p;
    cudaGetSymbolAddress(&p, g_a);  a  = (float*)p;
    cudaGetSymbolAddress(&p, g_b);  b  = (float*)p;
    cudaGetSymbolAddress(&p, g_c);  c  = (float*)p;
    cudaGetSymbolAddress(&p, g_z);  z  = (float*)p;
    cudaGetSymbolAddress(&p, g_q);  q  = (float*)p;

    // ---- encoder ----
    ew1_t<<<dim3(16,16,8), 256>>>(x, ew1, eb1, h1);
    conv4s2_t<<<dim3(8,16,16), 256>>>(h1, ew2, eb2, a);
    conv3_t<128,false,false,true><<<dim3(8,16,16), 256>>>(a, ew3, eb3, b, 128);
    conv3_t<128,true, false,false><<<dim3(8,16,4), 256>>>(b, er1a, nullptr, c, 32);
    conv1x1_t<32,true,false,true><<<dim3(16,16,8), 256>>>(c, er1b, nullptr, b, a, 128);
    conv3_t<128,true, false,false><<<dim3(8,16,4), 256>>>(a, er2a, nullptr, c, 32);
    conv1x1_t<32,true,false,true><<<dim3(16,16,8), 256>>>(c, er2b, nullptr, a, b, 128);
    conv1x1_t<128,true,true,false><<<dim3(16,16,4), 256>>>(b, pwW, pb, nullptr, z, 64);

    // ---- vector quantizer ----
    vq_prep<<<2, 256>>>(cb);
    vq_argmin<<<256, 256>>>(cb);
    fill_zero2<<<grd(16777216), 256>>>((float2*)(d_out + OFF_ENC), 16777216);
    vq_quant<<<256, 256>>>(cb, d_out + OFF_ENC, d_out + OFF_QUANT);
    vq_final<<<1, 512>>>(d_out);

    // ---- decoder ----
    conv3_t<64,false,false,true><<<dim3(8,16,16), 256>>>(q, dw1, db1, a, 128);
    conv3_t<128,true,false,false><<<dim3(8,16,4), 256>>>(a, dr1a, nullptr, c, 32);
    conv1x1_t<32,true,false,true><<<dim3(16,16,8), 256>>>(c, dr1b, nullptr, a, b, 128);
    conv3_t<128,true,false,false><<<dim3(8,16,4), 256>>>(b, dr2a, nullptr, c, 32);
    conv1x1_t<32,true,false,true><<<dim3(16,16,8), 256>>>(c, dr2b, nullptr, b, a, 128);
    convT1_t<<<dim3(8,16,32), 256>>>(a, dtw1, dtb1, h1);
    convT2_t<<<dim3(16,16,2), 256>>>(h1, dtw2, dtb2, d_out + OFF_XREC);
}